// round 3
// baseline (speedup 1.0000x reference)
#include <cuda_runtime.h>
#include <math.h>

#define BS 32
#define NA 8400
#define NC 80
#define NB 64
#define TOPKK 13

#define OFF_LABELS 0
#define OFF_BBOX   (BS*NA)              // 268800
#define OFF_SCORES (BS*NA + BS*NA*4)    // 1344000
#define OFF_FG     (OFF_SCORES + BS*NA*NC)  // 22848000
#define OFF_TGI    (OFF_FG + BS*NA)     // 23116800

// ---------------- scratch (static __device__: no allocations allowed) ----------------
__device__ float         g_overlaps[BS*NB*NA];   // masked clip(ciou,0)
__device__ float         g_align   [BS*NB*NA];   // score * ov^6 (masked)
__device__ unsigned char g_mask    [BS*NB*NA];   // topk ∧ in-gt ∧ mgt
__device__ float         g_posalign[BS*NB];
__device__ float         g_posover [BS*NB];
__device__ float         g_atanp   [BS*NA];
__device__ int           g_tgi     [BS*NA];
__device__ unsigned char g_fgb     [BS*NA];
__device__ float         g_amax    [BS*NA];
__device__ int           g_lab     [BS*NA];

// ---------------- K_clear: zero mask + pos accumulators ----------------
__global__ void k_clear()
{
    long i = (long)blockIdx.x * blockDim.x + threadIdx.x;
    const long n16 = (long)BS*NB*NA / 16;  // 1,075,200 int4s
    long stride = (long)gridDim.x * blockDim.x;
    for (long j = i; j < n16; j += stride)
        ((int4*)g_mask)[j] = make_int4(0,0,0,0);
    if (i < BS*NB) { g_posalign[i] = 0.f; g_posover[i] = 0.f; }
}

// zero the target_scores region of d_out (poisoned by harness)
__global__ void k_clear_scores(float4* p)
{
    long i = (long)blockIdx.x * blockDim.x + threadIdx.x;
    const long n = (long)BS*NA*NC / 4;  // 5,376,000
    if (i < n) p[i] = make_float4(0.f,0.f,0.f,0.f);
}

// ---------------- K_atanp: hoist atan(w2/h2) per pred box ----------------
__global__ void k_atanp(const float4* __restrict__ pd_bboxes)
{
    int i = blockIdx.x * blockDim.x + threadIdx.x;
    if (i < BS*NA) {
        float4 p = pd_bboxes[i];
        g_atanp[i] = atanf((p.z - p.x) / (p.w - p.y + 1e-7f));
    }
}

// ---------------- K_rows: per-(b,g) metric row + top-13 ----------------
__global__ __launch_bounds__(256) void k_rows(
    const float*  __restrict__ pd_scores,
    const float4* __restrict__ pd_bboxes,
    const float2* __restrict__ anc,
    const int*    __restrict__ gt_labels,
    const float4* __restrict__ gt_bboxes,
    const float*  __restrict__ mask_gt)
{
    int g = blockIdx.x, b = blockIdx.y;
    int row = b * NB + g;
    if (mask_gt[row] <= 0.f) return;  // ref forces these rows to contribute nothing

    __shared__ float s_al[NA];
    __shared__ float s_rv[256];
    __shared__ int   s_ri[256];

    float4 gb = gt_bboxes[row];
    int lbl = gt_labels[row];
    float w1 = gb.z - gb.x;
    float h1 = gb.w - gb.y + 1e-7f;
    float at1 = atanf(w1 / h1);
    float a1  = w1 * h1;

    const float*  sc  = pd_scores + (long)b * NA * NC + lbl;
    const float*  atp = g_atanp + b * NA;
    const float4* pb  = pd_bboxes + b * NA;
    int ro = row * NA;

    for (int a = threadIdx.x; a < NA; a += 256) {
        float2 ap = anc[a];
        float dmin = fminf(fminf(ap.x - gb.x, ap.y - gb.y),
                           fminf(gb.z - ap.x, gb.w - ap.y));
        bool inb = dmin > 1e-9f;

        float4 p = pb[a];
        float iw = fminf(gb.z, p.z) - fmaxf(gb.x, p.x);
        float ih = fminf(gb.w, p.w) - fmaxf(gb.y, p.y);
        float inter = fmaxf(iw, 0.f) * fmaxf(ih, 0.f);
        float w2 = p.z - p.x, h2 = p.w - p.y + 1e-7f;
        float uni = a1 + w2 * h2 - inter + 1e-7f;
        float iou = inter / uni;
        float cw = fmaxf(gb.z, p.z) - fminf(gb.x, p.x);
        float ch = fmaxf(gb.w, p.w) - fminf(gb.y, p.y);
        float c2 = cw * cw + ch * ch + 1e-7f;
        float dx = p.x + p.z - gb.x - gb.z;
        float dy = p.y + p.w - gb.y - gb.w;
        float rho2 = (dx * dx + dy * dy) * 0.25f;
        float dd = atp[a] - at1;
        float v = 0.4052847345693511f * dd * dd;   // 4/pi^2
        float alpha = v / (v - iou + (1.0f + 1e-7f));
        float ci = iou - (rho2 / c2 + v * alpha);

        float ov = inb ? fmaxf(ci, 0.f) : 0.f;
        float al = 0.f;
        if (ov > 0.f) {
            float s = sc[a * NC];
            float o2 = ov * ov;
            al = s * o2 * o2 * o2;    // score^1 * ov^6
        }
        g_overlaps[ro + a] = ov;
        g_align[ro + a]    = al;
        s_al[a] = al;
    }
    __syncthreads();

    // 13 iterative block argmaxes, lowest-index tie-break == jax.lax.top_k set
    for (int it = 0; it < TOPKK; ++it) {
        float bv = -2.f; int bi = NA;
        for (int a = threadIdx.x; a < NA; a += 256) {
            float v = s_al[a];
            if (v > bv) { bv = v; bi = a; }   // strides ascend → first occurrence kept
        }
        s_rv[threadIdx.x] = bv; s_ri[threadIdx.x] = bi;
        __syncthreads();
        for (int s = 128; s; s >>= 1) {
            if (threadIdx.x < s) {
                float v = s_rv[threadIdx.x + s]; int i = s_ri[threadIdx.x + s];
                if (v > s_rv[threadIdx.x] ||
                    (v == s_rv[threadIdx.x] && i < s_ri[threadIdx.x])) {
                    s_rv[threadIdx.x] = v; s_ri[threadIdx.x] = i;
                }
            }
            __syncthreads();
        }
        if (threadIdx.x == 0) {
            int idx = s_ri[0];
            float2 ap = anc[idx];
            float dmin = fminf(fminf(ap.x - gb.x, ap.y - gb.y),
                               fminf(gb.z - ap.x, gb.w - ap.y));
            if (dmin > 1e-9f) g_mask[ro + idx] = 1;  // mask_pos = topk ∧ in_gt ∧ mgt
            s_al[idx] = -1.f;
        }
        __syncthreads();
    }
}

// ---------------- K_assign: per-anchor dedup + targets + pos-max ----------------
__global__ __launch_bounds__(256) void k_assign(
    const int*    __restrict__ gt_labels,
    const float4* __restrict__ gt_bboxes,
    const float*  __restrict__ mask_gt,
    float* __restrict__ out)
{
    int b = blockIdx.y;
    __shared__ float s_mgt[NB];
    __shared__ int   s_lbl[NB];
    if (threadIdx.x < NB) {
        s_mgt[threadIdx.x] = mask_gt[b * NB + threadIdx.x];
        s_lbl[threadIdx.x] = gt_labels[b * NB + threadIdx.x];
    }
    __syncthreads();

    int a = blockIdx.x * blockDim.x + threadIdx.x;
    if (a >= NA) return;

    int base = b * NB * NA + a;
    int fg = 0, tgi0 = NB;
    #pragma unroll 8
    for (int g = 0; g < NB; ++g) {
        int m = g_mask[base + g * NA];
        fg += m;
        if (m && tgi0 == NB) tgi0 = g;
    }

    int tgi;
    if (fg > 1) {  // multi-assigned anchor -> argmax over overlaps (first-max on ties)
        float ovb = -1.f; int gbx = 0;
        for (int g = 0; g < NB; ++g) {
            float ov = (s_mgt[g] > 0.f) ? g_overlaps[base + g * NA] : 0.f;
            if (ov > ovb) { ovb = ov; gbx = g; }
        }
        tgi = gbx;
    } else {
        tgi = (tgi0 < NB) ? tgi0 : 0;
    }
    bool active = fg > 0;

    float am = 0.f, ovv = 0.f;
    if (active && s_mgt[tgi] > 0.f) {
        int q = b * NB * NA + tgi * NA + a;
        am  = g_align[q];
        ovv = g_overlaps[q];
    }
    if (active) {  // non-negative floats: int-compare atomicMax is exact
        atomicMax((int*)&g_posalign[b * NB + tgi], __float_as_int(am));
        atomicMax((int*)&g_posover [b * NB + tgi], __float_as_int(ovv));
    }

    int lab = max(s_lbl[tgi], 0);
    int ba = b * NA + a;
    g_tgi[ba] = tgi; g_fgb[ba] = active; g_amax[ba] = am; g_lab[ba] = lab;

    out[OFF_LABELS + ba] = (float)lab;
    ((float4*)(out + OFF_BBOX))[ba] = gt_bboxes[b * NB + tgi];
    out[OFF_FG  + ba] = active ? 1.f : 0.f;
    out[OFF_TGI + ba] = (float)tgi;
}

// ---------------- K_scores: scatter one-hot * norm into pre-zeroed region ----------------
__global__ void k_scores(float* __restrict__ out)
{
    int ba = blockIdx.x * blockDim.x + threadIdx.x;
    if (ba >= BS*NA) return;
    if (!g_fgb[ba]) return;
    int b = ba / NA;
    int tgi = g_tgi[ba];
    float pa = g_posalign[b * NB + tgi];
    float po = g_posover [b * NB + tgi];
    float norm = (g_amax[ba] * po) / (pa + 1e-9f);
    out[OFF_SCORES + (long)ba * NC + g_lab[ba]] = norm;
}

// ---------------- launch ----------------
extern "C" void kernel_launch(void* const* d_in, const int* in_sizes, int n_in,
                              void* d_out, int out_size)
{
    const float*  pd_scores = (const float*) d_in[0];
    const float4* pd_bboxes = (const float4*)d_in[1];
    const float2* anc       = (const float2*)d_in[2];
    const int*    gt_labels = (const int*)   d_in[3];
    const float4* gt_bboxes = (const float4*)d_in[4];
    const float*  mask_gt   = (const float*) d_in[5];
    float* out = (float*)d_out;

    k_clear<<<4224, 256>>>();
    k_clear_scores<<<(BS*NA*NC/4 + 255)/256, 256>>>((float4*)(out + OFF_SCORES));
    k_atanp<<<(BS*NA + 255)/256, 256>>>(pd_bboxes);

    dim3 grows(NB, BS);
    k_rows<<<grows, 256>>>(pd_scores, pd_bboxes, anc, gt_labels, gt_bboxes, mask_gt);

    dim3 gassign((NA + 255)/256, BS);
    k_assign<<<gassign, 256>>>(gt_labels, gt_bboxes, mask_gt, out);

    k_scores<<<(BS*NA + 255)/256, 256>>>(out);
}

// round 4
// speedup vs baseline: 1.5207x; 1.5207x over previous
#include <cuda_runtime.h>
#include <math.h>

#define BS 32
#define NA 8400
#define NC 80
#define NB 64
#define TOPKK 13
#define CAP 2048

#define OFF_LABELS 0
#define OFF_BBOX   (BS*NA)
#define OFF_SCORES (BS*NA + BS*NA*4)
#define OFF_FG     (OFF_SCORES + BS*NA*NC)
#define OFF_TGI    (OFF_FG + BS*NA)

// ---------------- scratch ----------------
__device__ float              g_overlaps[BS*NB*NA];   // masked clip(ciou,0)
__device__ unsigned long long g_maskbits[BS*NA];      // bit g = mask_pos(g,a) pre-dedup
__device__ float              g_posalign[BS*NB];
__device__ float              g_posover [BS*NB];
__device__ float              g_atanp   [BS*NA];
__device__ int                g_tgi     [BS*NA];
__device__ unsigned char      g_fgb     [BS*NA];
__device__ float              g_amax    [BS*NA];
__device__ int                g_lab     [BS*NA];

// ---------------- K_clear: zero maskbits + pos accumulators ----------------
__global__ void k_clear()
{
    int i = blockIdx.x * blockDim.x + threadIdx.x;
    const int n16 = BS*NA*8 / 16;   // 134400 int4s
    if (i < n16) ((int4*)g_maskbits)[i] = make_int4(0,0,0,0);
    if (i < BS*NB) { g_posalign[i] = 0.f; g_posover[i] = 0.f; }
}

// ---------------- K_atanp: hoist atan(w2/h2) per pred box ----------------
__global__ void k_atanp(const float4* __restrict__ pd_bboxes)
{
    int i = blockIdx.x * blockDim.x + threadIdx.x;
    if (i < BS*NA) {
        float4 p = pd_bboxes[i];
        g_atanp[i] = atanf((p.z - p.x) / (p.w - p.y + 1e-7f));
    }
}

// ---------------- K_rows: per-(b,g) metric row + compacted top-13 ----------------
__global__ __launch_bounds__(256) void k_rows(
    const float*  __restrict__ pd_scores,
    const float4* __restrict__ pd_bboxes,
    const float2* __restrict__ anc,
    const int*    __restrict__ gt_labels,
    const float4* __restrict__ gt_bboxes,
    const float*  __restrict__ mask_gt)
{
    int g = blockIdx.x, b = blockIdx.y;
    int row = b * NB + g;
    if (mask_gt[row] <= 0.f) return;   // masked rows contribute nothing (cnt>1 kill in ref)

    __shared__ int   s_cnt;
    __shared__ float s_cv[CAP];
    __shared__ int   s_ci[CAP];
    if (threadIdx.x == 0) s_cnt = 0;
    __syncthreads();

    float4 gb = gt_bboxes[row];
    int lbl = gt_labels[row];
    float w1 = gb.z - gb.x;
    float h1 = gb.w - gb.y + 1e-7f;
    float at1 = atanf(w1 / h1);
    float a1  = w1 * h1;

    const float*  sc  = pd_scores + (long)b * NA * NC + lbl;
    const float*  atp = g_atanp + b * NA;
    const float4* pb  = pd_bboxes + b * NA;
    long ro = (long)row * NA;

    for (int a = threadIdx.x; a < NA; a += 256) {
        float2 ap = anc[a];
        float dmin = fminf(fminf(ap.x - gb.x, ap.y - gb.y),
                           fminf(gb.z - ap.x, gb.w - ap.y));
        bool inb = dmin > 1e-9f;

        float4 p = pb[a];
        float iw = fminf(gb.z, p.z) - fmaxf(gb.x, p.x);
        float ih = fminf(gb.w, p.w) - fmaxf(gb.y, p.y);
        float inter = fmaxf(iw, 0.f) * fmaxf(ih, 0.f);
        float w2 = p.z - p.x, h2 = p.w - p.y + 1e-7f;
        float uni = a1 + w2 * h2 - inter + 1e-7f;
        float iou = inter / uni;
        float cw = fmaxf(gb.z, p.z) - fminf(gb.x, p.x);
        float ch = fmaxf(gb.w, p.w) - fminf(gb.y, p.y);
        float c2 = cw * cw + ch * ch + 1e-7f;
        float dx = p.x + p.z - gb.x - gb.z;
        float dy = p.y + p.w - gb.y - gb.w;
        float rho2 = (dx * dx + dy * dy) * 0.25f;
        float dd = atp[a] - at1;
        float v = 0.4052847345693511f * dd * dd;   // 4/pi^2
        float alpha = v / (v - iou + (1.0f + 1e-7f));
        float ci = iou - (rho2 / c2 + v * alpha);

        float ov = inb ? fmaxf(ci, 0.f) : 0.f;
        g_overlaps[ro + a] = ov;
        if (ov > 0.f) {
            float s = sc[a * NC];
            float o2 = ov * ov;
            float al = s * o2 * o2 * o2;     // score^1 * ov^6
            if (al > 0.f) {
                int pslot = atomicAdd(&s_cnt, 1);
                if (pslot < CAP) { s_cv[pslot] = al; s_ci[pslot] = a; }
            }
        }
    }
    __syncthreads();

    // warp 0: top-13 over candidates (ties -> lowest anchor index, == jax.lax.top_k)
    if (threadIdx.x < 32) {
        int lane = threadIdx.x;
        int C = min(s_cnt, CAP);
        int npos = min(C, TOPKK);
        for (int it = 0; it < npos; ++it) {
            float bv = -1.f; int bi = 0x7fffffff; int bj = -1;
            for (int j = lane; j < C; j += 32) {
                float v = s_cv[j]; int idx = s_ci[j];
                if (v > bv || (v == bv && idx < bi)) { bv = v; bi = idx; bj = j; }
            }
            #pragma unroll
            for (int off = 16; off; off >>= 1) {
                float vv = __shfl_down_sync(0xffffffffu, bv, off);
                int   ii = __shfl_down_sync(0xffffffffu, bi, off);
                int   jj = __shfl_down_sync(0xffffffffu, bj, off);
                if (vv > bv || (vv == bv && ii < bi)) { bv = vv; bi = ii; bj = jj; }
            }
            bj = __shfl_sync(0xffffffffu, bj, 0);
            bi = __shfl_sync(0xffffffffu, bi, 0);
            if (lane == 0) {
                atomicOr(&g_maskbits[b * NA + bi], 1ull << g);   // positives are in-box
                s_cv[bj] = -1.f;
            }
            __syncwarp();
        }
        // fewer than 13 positives: ref fills with lowest-index zero entries
        if (lane == 0 && C < TOPKK) {
            int rem = TOPKK - C;
            for (int a = 0; rem > 0 && a < NA; ++a) {
                bool pos = false;
                for (int j = 0; j < C; ++j) if (s_ci[j] == a) { pos = true; break; }
                if (pos) continue;
                rem--;                               // slot consumed by this zero entry
                float2 ap = anc[a];
                float dmin = fminf(fminf(ap.x - gb.x, ap.y - gb.y),
                                   fminf(gb.z - ap.x, gb.w - ap.y));
                if (dmin > 1e-9f)                    // mask only if in-box
                    atomicOr(&g_maskbits[b * NA + a], 1ull << g);
            }
        }
    }
}

// ---------------- K_assign: per-anchor dedup + targets + pos-max ----------------
__global__ __launch_bounds__(256) void k_assign(
    const float*  __restrict__ pd_scores,
    const int*    __restrict__ gt_labels,
    const float4* __restrict__ gt_bboxes,
    const float*  __restrict__ mask_gt,
    float* __restrict__ out)
{
    int b = blockIdx.y;
    __shared__ float s_mgt[NB];
    __shared__ int   s_lbl[NB];
    if (threadIdx.x < NB) {
        s_mgt[threadIdx.x] = mask_gt[b * NB + threadIdx.x];
        s_lbl[threadIdx.x] = gt_labels[b * NB + threadIdx.x];
    }
    __syncthreads();

    int a = blockIdx.x * blockDim.x + threadIdx.x;
    if (a >= NA) return;

    unsigned long long m = g_maskbits[b * NA + a];
    int fg = __popcll(m);
    long base = (long)b * NB * NA + a;

    int tgi;
    if (fg > 1) {   // multi-assigned anchor -> argmax over overlaps (first-max on ties)
        float ovb = -1.f; int gbx = 0;
        for (int g = 0; g < NB; ++g) {
            float ov = (s_mgt[g] > 0.f) ? g_overlaps[base + (long)g * NA] : 0.f;
            if (ov > ovb) { ovb = ov; gbx = g; }
        }
        tgi = gbx;
    } else {
        tgi = fg ? (__ffsll(m) - 1) : 0;
    }
    bool active = fg > 0;

    float am = 0.f, ovv = 0.f;
    if (active && s_mgt[tgi] > 0.f) {
        ovv = g_overlaps[base + (long)tgi * NA];
        if (ovv > 0.f) {
            float s = pd_scores[((long)b * NA + a) * NC + s_lbl[tgi]];
            float o2 = ovv * ovv;
            am = s * o2 * o2 * o2;    // bit-identical recompute of align metric
        }
    }
    if (active) {   // non-negative floats: int-compare atomicMax is exact
        atomicMax((int*)&g_posalign[b * NB + tgi], __float_as_int(am));
        atomicMax((int*)&g_posover [b * NB + tgi], __float_as_int(ovv));
    }

    int lab = max(s_lbl[tgi], 0);
    int ba = b * NA + a;
    g_tgi[ba] = tgi; g_fgb[ba] = active; g_amax[ba] = am; g_lab[ba] = lab;

    out[OFF_LABELS + ba] = (float)lab;
    ((float4*)(out + OFF_BBOX))[ba] = gt_bboxes[b * NB + tgi];
    out[OFF_FG  + ba] = active ? 1.f : 0.f;
    out[OFF_TGI + ba] = (float)tgi;
}

// ---------------- K_scores: zero rows + scatter one-hot * norm (fused) ----------------
__global__ __launch_bounds__(256) void k_scores(float* __restrict__ out)
{
    int ba0 = blockIdx.x * 256;                 // 256 anchor-rows per block
    float4* dst = (float4*)(out + OFF_SCORES + (long)ba0 * NC);
    for (int i = threadIdx.x; i < 256 * NC / 4; i += 256)
        dst[i] = make_float4(0.f, 0.f, 0.f, 0.f);
    __syncthreads();

    int ba = ba0 + threadIdx.x;
    if (ba < BS*NA && g_fgb[ba]) {
        int b = ba / NA;
        int tgi = g_tgi[ba];
        float pa = g_posalign[b * NB + tgi];
        float po = g_posover [b * NB + tgi];
        float norm = (g_amax[ba] * po) / (pa + 1e-9f);
        out[OFF_SCORES + (long)ba * NC + g_lab[ba]] = norm;
    }
}

// ---------------- launch ----------------
extern "C" void kernel_launch(void* const* d_in, const int* in_sizes, int n_in,
                              void* d_out, int out_size)
{
    const float*  pd_scores = (const float*) d_in[0];
    const float4* pd_bboxes = (const float4*)d_in[1];
    const float2* anc       = (const float2*)d_in[2];
    const int*    gt_labels = (const int*)   d_in[3];
    const float4* gt_bboxes = (const float4*)d_in[4];
    const float*  mask_gt   = (const float*) d_in[5];
    float* out = (float*)d_out;

    k_clear<<<(BS*NA*8/16 + 255)/256, 256>>>();
    k_atanp<<<(BS*NA + 255)/256, 256>>>(pd_bboxes);

    dim3 grows(NB, BS);
    k_rows<<<grows, 256>>>(pd_scores, pd_bboxes, anc, gt_labels, gt_bboxes, mask_gt);

    dim3 gassign((NA + 255)/256, BS);
    k_assign<<<gassign, 256>>>(pd_scores, gt_labels, gt_bboxes, mask_gt, out);

    k_scores<<<(BS*NA + 255)/256, 256>>>(out);
}

// round 5
// speedup vs baseline: 2.4896x; 1.6372x over previous
#include <cuda_runtime.h>
#include <math.h>

#define BS 32
#define NA 8400
#define NC 80
#define NB 64
#define TOPKK 13
#define CAP 512

#define OFF_LABELS 0
#define OFF_BBOX   (BS*NA)
#define OFF_SCORES (BS*NA + BS*NA*4)
#define OFF_FG     (OFF_SCORES + BS*NA*NC)
#define OFF_TGI    (OFF_FG + BS*NA)

// ---------------- scratch ----------------
__device__ unsigned long long g_maskbits[BS*NA];  // bit g = mask_pos(g,a) pre-dedup
__device__ unsigned long long g_pack   [BS*NA];   // max over valid g: (ov_bits<<8)|(63-g)
__device__ unsigned long long g_packsel[BS*NA];   // same pack, topk-selected pairs only
__device__ int                g_cnt [BS*NB];      // per-row candidate counts
__device__ unsigned long long g_key [BS*NB*CAP];  // (al_bits<<32)|(NA-1-a)
__device__ float              g_cov [BS*NB*CAP];  // candidate overlap
__device__ float              g_posalign[BS*NB];
__device__ float              g_posover [BS*NB];
__device__ int                g_tgi [BS*NA];
__device__ unsigned char      g_fgb [BS*NA];
__device__ float              g_amax[BS*NA];
__device__ int                g_lab [BS*NA];

// ---------------- K_clear ----------------
__global__ void k_clear()
{
    int i = blockIdx.x * blockDim.x + threadIdx.x;
    int4 z = make_int4(0,0,0,0);
    const int n4 = BS*NA*8/16;   // 134400 int4 per u64 array
    if (i < n4) { ((int4*)g_maskbits)[i] = z; ((int4*)g_packsel)[i] = z; }
    if (i < BS*NB) { g_cnt[i] = 0; g_posalign[i] = 0.f; g_posover[i] = 0.f; }
}

// ---------------- K_main: per-(b,anchor) over all gts in smem ----------------
__global__ __launch_bounds__(256) void k_main(
    const float*  __restrict__ pd_scores,
    const float4* __restrict__ pd_bboxes,
    const float2* __restrict__ anc,
    const int*    __restrict__ gt_labels,
    const float4* __restrict__ gt_bboxes,
    const float*  __restrict__ mask_gt)
{
    int b = blockIdx.y;
    __shared__ float4        s_box[NB];
    __shared__ float         s_at1[NB], s_a1[NB];
    __shared__ int           s_lbl[NB];
    __shared__ unsigned char s_v[NB];

    if (threadIdx.x < NB) {
        int g = threadIdx.x;
        float4 G = gt_bboxes[b*NB + g];
        s_box[g] = G;
        s_lbl[g] = gt_labels[b*NB + g];
        s_v[g]   = mask_gt[b*NB + g] > 0.f;
        float w1 = G.z - G.x, h1 = G.w - G.y + 1e-7f;
        s_at1[g] = atanf(w1 / h1);
        s_a1[g]  = w1 * h1;
    }
    __syncthreads();

    int a = blockIdx.x * 256 + threadIdx.x;
    if (a >= NA) return;

    float2 ap = anc[a];
    float4 p  = pd_bboxes[b*NA + a];
    float w2 = p.z - p.x, h2 = p.w - p.y + 1e-7f;
    float at2 = atanf(w2 / h2);
    float wh2 = w2 * h2;
    const float* sc = pd_scores + ((long)b*NA + a) * NC;

    unsigned long long packall = 0;

    #pragma unroll 4
    for (int g = 0; g < NB; ++g) {
        if (!s_v[g]) continue;
        float4 G = s_box[g];
        float dmin = fminf(fminf(ap.x - G.x, ap.y - G.y),
                           fminf(G.z - ap.x, G.w - ap.y));
        if (dmin <= 1e-9f) continue;   // not inside gt -> masked to 0 everywhere

        float iw = fminf(G.z, p.z) - fmaxf(G.x, p.x);
        float ih = fminf(G.w, p.w) - fmaxf(G.y, p.y);
        float inter = fmaxf(iw, 0.f) * fmaxf(ih, 0.f);
        float uni = s_a1[g] + wh2 - inter + 1e-7f;
        float iou = inter / uni;
        float cw = fmaxf(G.z, p.z) - fminf(G.x, p.x);
        float ch = fmaxf(G.w, p.w) - fminf(G.y, p.y);
        float c2 = cw*cw + ch*ch + 1e-7f;
        float dx = p.x + p.z - G.x - G.z;
        float dy = p.y + p.w - G.y - G.w;
        float rho2 = (dx*dx + dy*dy) * 0.25f;
        float dd = at2 - s_at1[g];
        float v = 0.4052847345693511f * dd * dd;   // 4/pi^2
        float alpha = v / (v - iou + (1.0f + 1e-7f));
        float ci = iou - (rho2 / c2 + v * alpha);
        float ov = fmaxf(ci, 0.f);
        if (ov <= 0.f) continue;

        // per-anchor argmax over g (ties -> lowest g, like jnp.argmax)
        unsigned long long pk =
            ((unsigned long long)__float_as_uint(ov) << 8) | (unsigned)(63 - g);
        packall = max(packall, pk);

        float s  = sc[s_lbl[g]];
        float o2 = ov * ov;
        float al = s * o2 * o2 * o2;   // score^1 * ov^6
        if (al > 0.f) {
            int row = b * NB + g;
            int slot = atomicAdd(&g_cnt[row], 1);
            if (slot < CAP) {
                g_key[(long)row*CAP + slot] =
                    ((unsigned long long)__float_as_uint(al) << 32) | (unsigned)(NA - 1 - a);
                g_cov[(long)row*CAP + slot] = ov;
            }
        }
    }
    g_pack[b*NA + a] = packall;
}

// ---------------- K_top: per-row top-13 over compacted candidates ----------------
__global__ void k_top(
    const float2* __restrict__ anc,
    const float4* __restrict__ gt_bboxes,
    const float*  __restrict__ mask_gt)
{
    int g = blockIdx.x, b = blockIdx.y;
    int row = b*NB + g;
    if (mask_gt[row] <= 0.f) return;   // masked rows killed by cnt>1 in ref
    int lane = threadIdx.x;

    __shared__ unsigned long long s_key[CAP];
    __shared__ float s_cov[CAP];
    __shared__ int   s_ca[CAP];

    int C = min(g_cnt[row], CAP);
    for (int j = lane; j < C; j += 32) {
        unsigned long long k = g_key[(long)row*CAP + j];
        s_key[j] = k;
        s_cov[j] = g_cov[(long)row*CAP + j];
        s_ca[j]  = NA - 1 - (int)(k & 0xffffffffull);
    }
    __syncwarp();

    int npos = min(C, TOPKK);
    for (int it = 0; it < npos; ++it) {
        unsigned long long bk = 0; int bj = -1;
        for (int j = lane; j < C; j += 32) {
            unsigned long long k = s_key[j];
            if (k > bk) { bk = k; bj = j; }
        }
        #pragma unroll
        for (int off = 16; off; off >>= 1) {
            unsigned long long kk = __shfl_down_sync(0xffffffffu, bk, off);
            int jj = __shfl_down_sync(0xffffffffu, bj, off);
            if (kk > bk) { bk = kk; bj = jj; }
        }
        bj = __shfl_sync(0xffffffffu, bj, 0);
        if (lane == 0) {
            int a = s_ca[bj];
            atomicOr(&g_maskbits[b*NA + a], 1ull << g);  // positives are in-box
            unsigned long long pk =
                ((unsigned long long)__float_as_uint(s_cov[bj]) << 8) | (unsigned)(63 - g);
            atomicMax(&g_packsel[b*NA + a], pk);
            s_key[bj] = 0;
        }
        __syncwarp();
    }

    // fewer than 13 positives: ref fills with lowest-index zero entries
    if (lane == 0 && C < TOPKK) {
        float4 G = gt_bboxes[row];
        int rem = TOPKK - C;
        for (int a = 0; rem > 0 && a < NA; ++a) {
            bool member = false;
            for (int j = 0; j < C; ++j) if (s_ca[j] == a) { member = true; break; }
            if (member) continue;
            rem--;                                  // slot consumed by this zero entry
            float2 ap = anc[a];
            float dmin = fminf(fminf(ap.x - G.x, ap.y - G.y),
                               fminf(G.z - ap.x, G.w - ap.y));
            if (dmin > 1e-9f)                       // mask only if in-box (ov=0 -> no packsel)
                atomicOr(&g_maskbits[b*NA + a], 1ull << g);
        }
    }
}

// ---------------- K_assign: dedup + targets + pos-max + fused score zero-fill ----------------
__global__ __launch_bounds__(256) void k_assign(
    const float*  __restrict__ pd_scores,
    const int*    __restrict__ gt_labels,
    const float4* __restrict__ gt_bboxes,
    float* __restrict__ out)
{
    int b = blockIdx.y;
    int a0 = blockIdx.x * 256;

    // zero this block's slice of the target_scores region (poisoned by harness)
    {
        int cnt = min(256, NA - a0);
        float4* dst = (float4*)(out + OFF_SCORES + ((long)b*NA + a0) * NC);
        int n4 = cnt * NC / 4;
        float4 z = make_float4(0.f,0.f,0.f,0.f);
        for (int i = threadIdx.x; i < n4; i += 256) dst[i] = z;
    }

    __shared__ int s_lbl[NB];
    if (threadIdx.x < NB) s_lbl[threadIdx.x] = gt_labels[b*NB + threadIdx.x];
    __syncthreads();

    int a = a0 + threadIdx.x;
    if (a >= NA) return;
    int ba = b*NA + a;

    unsigned long long m = g_maskbits[ba];
    int fg = __popcll(m);
    int tgi = 0; float ovv = 0.f;
    if (fg > 1) {               // multi-assigned -> argmax over masked overlaps (all g)
        unsigned long long pk = g_pack[ba];
        if (pk) {
            tgi = 63 - (int)(pk & 63ull);
            ovv = __uint_as_float((unsigned)(pk >> 8));
        }
    } else if (fg == 1) {
        tgi = __ffsll((long long)m) - 1;
        unsigned long long ps = g_packsel[ba];
        ovv = __uint_as_float((unsigned)(ps >> 8));
    }
    bool active = fg > 0;

    float am = 0.f;
    if (active && ovv > 0.f) {
        float s = pd_scores[((long)b*NA + a) * NC + s_lbl[tgi]];
        float o2 = ovv * ovv;
        am = s * o2 * o2 * o2;   // identical recompute of align metric
    }
    if (active) {   // non-negative floats: int-compare atomicMax is exact
        atomicMax((int*)&g_posalign[b*NB + tgi], __float_as_int(am));
        atomicMax((int*)&g_posover [b*NB + tgi], __float_as_int(ovv));
    }

    int lab = max(s_lbl[tgi], 0);
    g_tgi[ba] = tgi; g_fgb[ba] = active; g_amax[ba] = am; g_lab[ba] = lab;

    out[OFF_LABELS + ba] = (float)lab;
    ((float4*)(out + OFF_BBOX))[ba] = gt_bboxes[b*NB + tgi];
    out[OFF_FG  + ba] = active ? 1.f : 0.f;
    out[OFF_TGI + ba] = (float)tgi;
}

// ---------------- K_scores: scatter one-hot * norm ----------------
__global__ void k_scores(float* __restrict__ out)
{
    int ba = blockIdx.x * blockDim.x + threadIdx.x;
    if (ba >= BS*NA) return;
    if (!g_fgb[ba]) return;
    int b = ba / NA;
    int tgi = g_tgi[ba];
    float pa = g_posalign[b*NB + tgi];
    float po = g_posover [b*NB + tgi];
    out[OFF_SCORES + (long)ba * NC + g_lab[ba]] = (g_amax[ba] * po) / (pa + 1e-9f);
}

// ---------------- launch ----------------
extern "C" void kernel_launch(void* const* d_in, const int* in_sizes, int n_in,
                              void* d_out, int out_size)
{
    const float*  pd_scores = (const float*) d_in[0];
    const float4* pd_bboxes = (const float4*)d_in[1];
    const float2* anc       = (const float2*)d_in[2];
    const int*    gt_labels = (const int*)   d_in[3];
    const float4* gt_bboxes = (const float4*)d_in[4];
    const float*  mask_gt   = (const float*) d_in[5];
    float* out = (float*)d_out;

    k_clear<<<(BS*NA*8/16 + 255)/256, 256>>>();

    dim3 gmain((NA + 255)/256, BS);
    k_main<<<gmain, 256>>>(pd_scores, pd_bboxes, anc, gt_labels, gt_bboxes, mask_gt);

    dim3 gtop(NB, BS);
    k_top<<<gtop, 32>>>(anc, gt_bboxes, mask_gt);

    dim3 gassign((NA + 255)/256, BS);
    k_assign<<<gassign, 256>>>(pd_scores, gt_labels, gt_bboxes, out);

    k_scores<<<(BS*NA + 255)/256, 256>>>(out);
}